// round 15
// baseline (speedup 1.0000x reference)
#include <cuda_runtime.h>
#include <cuda_bf16.h>
#include <cstdint>

#define N_MAX 100000
#define DD 512
#define HH 32

// ---------------- scratch (static __device__, allocation-free) ----------------
static __device__ float         g_qemb[N_MAX * HH];  // f32
static __device__ __nv_bfloat16 g_kemb_bf[N_MAX * HH];
static __device__ __nv_bfloat16 g_attn_bf[N_MAX * HH];
static __device__ int           g_ctr1;              // gemm1 tiles   (reset by attn)
static __device__ int           g_ctr2;              // gemm2 tiles   (reset by attn)
static __device__ int           g_ctr3;              // attn chunks   (reset by gemm1)

// ---------------- helpers ----------------
__device__ __forceinline__ float nonneg(float w) { return w > 0.f ? w + 1.f : __expf(w); }

__device__ __forceinline__ uint32_t s2u(const void* p) {
    return (uint32_t)__cvta_generic_to_shared(p);
}

__device__ __forceinline__ void ldsm4(uint32_t (&r)[4], uint32_t addr) {
    asm volatile("ldmatrix.sync.aligned.m8n8.x4.shared.b16 {%0,%1,%2,%3}, [%4];"
                 : "=r"(r[0]), "=r"(r[1]), "=r"(r[2]), "=r"(r[3]) : "r"(addr));
}

__device__ __forceinline__ void mma16816(float (&d)[4], const uint32_t (&a)[4],
                                         uint32_t b0, uint32_t b1) {
    asm volatile(
        "mma.sync.aligned.m16n8k16.row.col.f32.bf16.bf16.f32 "
        "{%0,%1,%2,%3}, {%4,%5,%6,%7}, {%8,%9}, {%0,%1,%2,%3};"
        : "+f"(d[0]), "+f"(d[1]), "+f"(d[2]), "+f"(d[3])
        : "r"(a[0]), "r"(a[1]), "r"(a[2]), "r"(a[3]), "r"(b0), "r"(b1));
}

__device__ __forceinline__ void cp_async16(void* s, const void* g) {
    asm volatile("cp.async.cg.shared.global [%0], [%1], 16;"
                 :: "r"(s2u(s)), "l"(g));
}
__device__ __forceinline__ void cp_commit() { asm volatile("cp.async.commit_group;"); }
template <int NN>
__device__ __forceinline__ void cp_wait() { asm volatile("cp.async.wait_group %0;" :: "n"(NN)); }

__device__ __forceinline__ uint32_t bf2u(float a, float b) {
    __nv_bfloat162 p = __floats2bfloat162_rn(a, b);
    return *(uint32_t*)&p;
}

__device__ __forceinline__ void pdl_trigger() {
    asm volatile("griddepcontrol.launch_dependents;" ::: "memory");
}
__device__ __forceinline__ void pdl_wait() {
    asm volatile("griddepcontrol.wait;" ::: "memory");
}

// ---------------- K1: GEMM1  qk_emb = x @ Wqk^T  (mma.sync bf16, XOR swizzle) ----------------
// 256 thr, 2 CTAs/SM (measured 54.9-55.5us). W 64KB XOR-swizzled. x dbuf bf16 tiles.
// STS-first mainloop; warp tile 32 rows x 32 ch. Dynamic tiles via g_ctr1.
// Also resets g_ctr3 (attn chunk counter) for this replay.
#define G1_A0   65536
#define G1_A1   81920
#define G1_SMEM 98304

__global__ void __launch_bounds__(256, 2) gemm1_kernel(const float* __restrict__ x,
                                                       const float* __restrict__ qw,
                                                       const float* __restrict__ kw, int n) {
    extern __shared__ __align__(16) char sm[];
    __shared__ int stile;
    const int tid  = threadIdx.x;
    const int lane = tid & 31;
    const int warp = tid >> 5;

    if (blockIdx.x == 0 && tid == 0) g_ctr3 = 0;  // attn reads it only after PDL wait

    // one-time: W = nonneg(qw/kw)/512 -> bf16 smem, row ch = 1024B, XOR swizzle
    for (int u = tid; u < 4096; u += 256) {
        int ch = u >> 6, seg = u & 63;
        const float* src = (ch < 32) ? (qw + ch * DD) : (kw + (ch - 32) * DD);
        float4 f0 = __ldg((const float4*)(src + seg * 8));
        float4 f1 = __ldg((const float4*)(src + seg * 8) + 1);
        const float sc = 1.f / (float)DD;
        uint4 pk;
        pk.x = bf2u(nonneg(f0.x) * sc, nonneg(f0.y) * sc);
        pk.y = bf2u(nonneg(f0.z) * sc, nonneg(f0.w) * sc);
        pk.z = bf2u(nonneg(f1.x) * sc, nonneg(f1.y) * sc);
        pk.w = bf2u(nonneg(f1.z) * sc, nonneg(f1.w) * sc);
        *(uint4*)(sm + ch * 1024 + ((seg * 16) ^ ((ch & 7) << 4))) = pk;
    }

    const int mrow = (warp & 3) * 32;  // row slice within 128-row tile
    const int chb  = (warp >> 2) * 32; // ch slice: warps 0-3 -> q, 4-7 -> k
    const uint32_t swz  = (uint32_t)((lane & 7) << 4);
    const uint32_t wrow = s2u(sm) + (uint32_t)(chb + (lane & 7) + ((lane >> 4) << 3)) * 1024u;
    const uint32_t whi  = (uint32_t)(((lane >> 3) & 1) << 4);
    const uint32_t ahi  = (uint32_t)(((lane >> 4) & 1) << 4);

    const int ntiles = (n + 127) >> 7;
    if (tid == 0) stile = atomicAdd(&g_ctr1, 1);
    __syncthreads();  // W ready + stile visible
    int tile = stile;

    while (tile < ntiles) {
        const int row0 = tile << 7;
        float acc[2][4][4];
        #pragma unroll
        for (int m = 0; m < 2; m++)
            #pragma unroll
            for (int nt = 0; nt < 4; nt++)
                #pragma unroll
                for (int j = 0; j < 4; j++) acc[m][nt][j] = 0.f;

        float4 v[4][2];
        // prologue: LDG(0) -> STS buf0 -> LDG(1)
        #pragma unroll
        for (int u = 0; u < 4; u++) {
            int idx = tid + (u << 8);
            int row = idx >> 3, seg = idx & 7;
            int gr = row0 + row; if (gr >= n) gr = n - 1;
            const float4* src = (const float4*)(x + (size_t)gr * DD + seg * 8);
            v[u][0] = __ldg(src); v[u][1] = __ldg(src + 1);
        }
        #pragma unroll
        for (int u = 0; u < 4; u++) {
            int idx = tid + (u << 8);
            int row = idx >> 3, seg = idx & 7;
            uint4 pk;
            pk.x = bf2u(v[u][0].x, v[u][0].y); pk.y = bf2u(v[u][0].z, v[u][0].w);
            pk.z = bf2u(v[u][1].x, v[u][1].y); pk.w = bf2u(v[u][1].z, v[u][1].w);
            *(uint4*)(sm + G1_A0 + row * 128 + ((seg * 16) ^ ((row & 7) << 4))) = pk;
        }
        #pragma unroll
        for (int u = 0; u < 4; u++) {
            int idx = tid + (u << 8);
            int row = idx >> 3, seg = idx & 7;
            int gr = row0 + row; if (gr >= n) gr = n - 1;
            const float4* src = (const float4*)(x + (size_t)gr * DD + 64 + seg * 8);
            v[u][0] = __ldg(src); v[u][1] = __ldg(src + 1);
        }
        __syncthreads();

        #pragma unroll 1
        for (int c = 0; c < 8; c++) {
            if (c < 7) {  // STS chunk c+1 (regs landed one full iteration ago)
                char* nbuf = sm + ((c & 1) ? G1_A0 : G1_A1);
                #pragma unroll
                for (int u = 0; u < 4; u++) {
                    int idx = tid + (u << 8);
                    int row = idx >> 3, seg = idx & 7;
                    uint4 pk;
                    pk.x = bf2u(v[u][0].x, v[u][0].y); pk.y = bf2u(v[u][0].z, v[u][0].w);
                    pk.z = bf2u(v[u][1].x, v[u][1].y); pk.w = bf2u(v[u][1].z, v[u][1].w);
                    *(uint4*)(nbuf + row * 128 + ((seg * 16) ^ ((row & 7) << 4))) = pk;
                }
            }
            if (c < 6) {  // LDG chunk c+2
                #pragma unroll
                for (int u = 0; u < 4; u++) {
                    int idx = tid + (u << 8);
                    int row = idx >> 3, seg = idx & 7;
                    int gr = row0 + row; if (gr >= n) gr = n - 1;
                    const float4* src = (const float4*)(x + (size_t)gr * DD + (c + 2) * 64 + seg * 8);
                    v[u][0] = __ldg(src); v[u][1] = __ldg(src + 1);
                }
            }
            // MMA on chunk c
            const uint32_t abase = s2u(sm) + (uint32_t)((c & 1) ? G1_A1 : G1_A0);
            const uint32_t arow0 = abase + (uint32_t)(mrow + (lane & 15)) * 128u;
            #pragma unroll
            for (int ks = 0; ks < 4; ks++) {
                uint32_t a0[4], a1[4], b0[4], b1[4];
                uint32_t akb = ((uint32_t)(ks * 32) + ahi) ^ swz;
                uint32_t wkb = (uint32_t)(c * 128) + (((uint32_t)(ks * 32) + whi) ^ swz);
                ldsm4(a0, arow0 + akb);
                ldsm4(a1, arow0 + 16u * 128u + akb);
                ldsm4(b0, wrow + wkb);
                ldsm4(b1, wrow + 16u * 1024u + wkb);
                mma16816(acc[0][0], a0, b0[0], b0[1]);
                mma16816(acc[0][1], a0, b0[2], b0[3]);
                mma16816(acc[0][2], a0, b1[0], b1[1]);
                mma16816(acc[0][3], a0, b1[2], b1[3]);
                mma16816(acc[1][0], a1, b0[0], b0[1]);
                mma16816(acc[1][1], a1, b0[2], b0[3]);
                mma16816(acc[1][2], a1, b1[0], b1[1]);
                mma16816(acc[1][3], a1, b1[2], b1[3]);
            }
            __syncthreads();
        }

        // epilogue: warps 0-3 -> q f32, warps 4-7 -> k bf16
        #pragma unroll
        for (int m = 0; m < 2; m++) {
            int r0 = row0 + mrow + m * 16 + (lane >> 2);
            #pragma unroll
            for (int nt = 0; nt < 4; nt++) {
                int ch = nt * 8 + (lane & 3) * 2;
                if (warp < 4) {
                    if (r0 < n)
                        *(float2*)(g_qemb + (size_t)r0 * HH + ch) = make_float2(acc[m][nt][0], acc[m][nt][1]);
                    if (r0 + 8 < n)
                        *(float2*)(g_qemb + (size_t)(r0 + 8) * HH + ch) = make_float2(acc[m][nt][2], acc[m][nt][3]);
                } else {
                    if (r0 < n)
                        *(uint32_t*)(g_kemb_bf + (size_t)r0 * HH + ch) = bf2u(acc[m][nt][0], acc[m][nt][1]);
                    if (r0 + 8 < n)
                        *(uint32_t*)(g_kemb_bf + (size_t)(r0 + 8) * HH + ch) = bf2u(acc[m][nt][2], acc[m][nt][3]);
                }
            }
        }

        if (tid == 0) stile = atomicAdd(&g_ctr1, 1);
        __syncthreads();
        tile = stile;
    }
    pdl_trigger();
}

// ---------------- K2: gather + attention normalize (dynamic 32-node chunks) ----------------
// Warp grabs a 32-node chunk (8 x 4-node groups) via g_ctr3; 32 outstanding uint2 gathers
// per group. PDL: waits for gemm1; resets g_ctr1/g_ctr2 for downstream/next replay.
__global__ void __launch_bounds__(256) attn_kernel(const int* __restrict__ src,
                                                   const float* __restrict__ eg, int n) {
    const int lane = threadIdx.x & 31;
    const int jg   = lane >> 3;
    const int hp   = lane & 7;
    float4 eraw = __ldg((const float4*)(eg + hp * 4));
    const float4 ego = make_float4(nonneg(eraw.x), nonneg(eraw.y), nonneg(eraw.z), nonneg(eraw.w));
    const float k1 = 1.f / 32.f;

    pdl_wait();  // gemm1 complete: k_emb/q_emb valid, counters safe to reset
    if (blockIdx.x == 0 && threadIdx.x == 0) { g_ctr1 = 0; g_ctr2 = 0; }

    const int nchunks = (n + 31) >> 5;
    for (;;) {
        int ck;
        if (lane == 0) ck = atomicAdd(&g_ctr3, 1);
        ck = __shfl_sync(0xffffffffu, ck, 0);
        if (ck >= nchunks) break;
        const int cbase = ck << 5;

        #pragma unroll 1
        for (int g = 0; g < 8; g++) {
            const int node = cbase + (g << 2);
            if (node >= n) break;

            int nd[4];
            #pragma unroll
            for (int u = 0; u < 4; u++) nd[u] = (node + u < n) ? node + u : node;

            int s[4];
            #pragma unroll
            for (int u = 0; u < 4; u++) s[u] = src[(size_t)nd[u] * 32 + lane];

            float ac[4][4];
            #pragma unroll
            for (int u = 0; u < 4; u++)
                #pragma unroll
                for (int j = 0; j < 4; j++) ac[u][j] = 0.f;

            #pragma unroll
            for (int i = 0; i < 8; i++) {
                #pragma unroll
                for (int u = 0; u < 4; u++) {
                    int sj = __shfl_sync(0xffffffffu, s[u], i * 4 + jg);
                    uint2 kv = __ldg((const uint2*)(g_kemb_bf + (size_t)sj * HH + hp * 4));
                    float2 f0 = __bfloat1622float2(*(__nv_bfloat162*)&kv.x);
                    float2 f1 = __bfloat1622float2(*(__nv_bfloat162*)&kv.y);
                    ac[u][0] += f0.x; ac[u][1] += f0.y; ac[u][2] += f1.x; ac[u][3] += f1.y;
                }
            }
            #pragma unroll
            for (int u = 0; u < 4; u++)
                #pragma unroll
                for (int j = 0; j < 4; j++) {
                    ac[u][j] += __shfl_xor_sync(0xffffffffu, ac[u][j], 8);
                    ac[u][j] += __shfl_xor_sync(0xffffffffu, ac[u][j], 16);
                }

            float sc[4][4], nsum[4];
            #pragma unroll
            for (int u = 0; u < 4; u++) {
                float4 q = *(const float4*)(g_qemb + (size_t)nd[u] * HH + hp * 4);
                sc[u][0] = ego.x * q.x * q.x + q.x * ac[u][0] * k1;
                sc[u][1] = ego.y * q.y * q.y + q.y * ac[u][1] * k1;
                sc[u][2] = ego.z * q.z * q.z + q.z * ac[u][2] * k1;
                sc[u][3] = ego.w * q.w * q.w + q.w * ac[u][3] * k1;
                nsum[u] = (sc[u][0] + sc[u][1]) + (sc[u][2] + sc[u][3]);
            }
            #pragma unroll
            for (int u = 0; u < 4; u++) {
                nsum[u] += __shfl_xor_sync(0xffffffffu, nsum[u], 1);
                nsum[u] += __shfl_xor_sync(0xffffffffu, nsum[u], 2);
                nsum[u] += __shfl_xor_sync(0xffffffffu, nsum[u], 4);
            }

            if (jg == 0) {
                #pragma unroll
                for (int u = 0; u < 4; u++) {
                    if (u == 0 || node + u < n) {
                        float inv = 1.f / (nsum[u] + 1e-9f);
                        uint2 pk;
                        pk.x = bf2u(sc[u][0] * inv, sc[u][1] * inv);
                        pk.y = bf2u(sc[u][2] * inv, sc[u][3] * inv);
                        *(uint2*)(g_attn_bf + (size_t)nd[u] * HH + hp * 4) = pk;
                    }
                }
            }
        }
    }
    pdl_trigger();
}

// ---------------- K3: GEMM2  out = attn @ V'  (mma.sync bf16, dynamic tiles) ----------------
// 512 thr, 16 warps. Warp = 16 nodes x 64 d. V frags hoisted. Dynamic 256-node tiles
// via g_ctr2 with pipelined grab (tile for iter i+2 fetched during iter i).
#define G2_VPITCH 80
#define G2_A0     40960
#define G2_A1     61440
#define G2_SMEM   81920

__global__ void __launch_bounds__(512, 1) gemm2_kernel(float* __restrict__ out,
                                                       const float* __restrict__ vw, int n) {
    extern __shared__ __align__(16) char sm[];
    __shared__ int s_t[2];
    const int tid  = threadIdx.x;
    const int lane = tid & 31;
    const int warp = tid >> 5;

    // one-time: V [512][32] f32 -> nonneg -> bf16 smem, pitch 80B (runs under PDL overlap)
    for (int i = tid; i < 2048; i += 512) {
        int d = i >> 2, seg = i & 3;
        const float4* src = (const float4*)(vw + d * HH + seg * 8);
        float4 f0 = __ldg(src), f1 = __ldg(src + 1);
        uint4 pk;
        pk.x = bf2u(nonneg(f0.x), nonneg(f0.y));
        pk.y = bf2u(nonneg(f0.z), nonneg(f0.w));
        pk.z = bf2u(nonneg(f1.x), nonneg(f1.y));
        pk.w = bf2u(nonneg(f1.z), nonneg(f1.w));
        *(uint4*)(sm + d * G2_VPITCH + seg * 16) = pk;
    }
    __syncthreads();

    const int nsl   = (warp & 1) * 16;   // node sub-slice within 32-node subtile
    const int dbase = (warp >> 1) * 64;  // d slice: 8 groups x 64 = 512

    // hoist V fragments: [kstep][ptile][4 regs]
    uint32_t bf[2][4][4];
    {
        uint32_t vb = s2u(sm) + (uint32_t)(dbase + (lane & 7) + ((lane >> 4) << 3)) * G2_VPITCH
                    + (uint32_t)(((lane >> 3) & 1) << 4);
        #pragma unroll
        for (int ks = 0; ks < 2; ks++)
            #pragma unroll
            for (int p = 0; p < 4; p++)
                ldsm4(bf[ks][p], vb + (uint32_t)(p * 16 * G2_VPITCH) + (uint32_t)(ks * 32));
    }
    __syncthreads();

    pdl_wait();  // attn complete: g_attn_bf valid, g_ctr2 reset

    const int ntiles = (n + 255) >> 8;
    if (tid == 0) s_t[0] = atomicAdd(&g_ctr2, 1);
    __syncthreads();
    int t = s_t[0];
    int cur = 0, it = 0;
    if (t < ntiles) {
        int n0 = t << 8;
        #pragma unroll
        for (int u = 0; u < 2; u++) {
            int idx = tid + (u << 9);
            int row = idx >> 2, seg = idx & 3;
            int node = n0 + row; if (node >= n) node = n - 1;
            cp_async16(sm + G2_A0 + row * G2_VPITCH + seg * 16,
                       g_attn_bf + (size_t)node * HH + seg * 8);
        }
    }
    cp_commit();
    if (tid == 0) s_t[1] = atomicAdd(&g_ctr2, 1);

    while (t < ntiles) {
        __syncthreads();  // s_t[(it+1)&1] visible
        int tn = s_t[(it + 1) & 1];
        if (tn < ntiles) {
            int n0 = tn << 8;
            char* dst = sm + (cur ? G2_A0 : G2_A1);
            #pragma unroll
            for (int u = 0; u < 2; u++) {
                int idx = tid + (u << 9);
                int row = idx >> 2, seg = idx & 3;
                int node = n0 + row; if (node >= n) node = n - 1;
                cp_async16(dst + row * G2_VPITCH + seg * 16,
                           g_attn_bf + (size_t)node * HH + seg * 8);
            }
        }
        cp_commit();
        if (tid == 0) s_t[it & 1] = atomicAdd(&g_ctr2, 1);  // tile for iteration it+2
        cp_wait<1>();     // current tile's data landed
        __syncthreads();

        const char* ab = sm + (cur ? G2_A1 : G2_A0);
        const int node0 = t << 8;
        #pragma unroll 1
        for (int sub = 0; sub < 8; sub++) {
            uint32_t a[2][4];
            uint32_t aaddr = s2u(ab) + (uint32_t)((sub * 32 + nsl + (lane & 15)) * G2_VPITCH)
                           + (uint32_t)(((lane >> 4) & 1) << 4);
            ldsm4(a[0], aaddr);
            ldsm4(a[1], aaddr + 32);

            float acc[8][4];
            #pragma unroll
            for (int nt = 0; nt < 8; nt++)
                #pragma unroll
                for (int j = 0; j < 4; j++) acc[nt][j] = 0.f;

            #pragma unroll
            for (int nt = 0; nt < 8; nt++) {
                mma16816(acc[nt], a[0], bf[0][nt >> 1][(nt & 1) * 2], bf[0][nt >> 1][(nt & 1) * 2 + 1]);
                mma16816(acc[nt], a[1], bf[1][nt >> 1][(nt & 1) * 2], bf[1][nt >> 1][(nt & 1) * 2 + 1]);
            }

            int r0 = node0 + sub * 32 + nsl + (lane >> 2);
            #pragma unroll
            for (int nt = 0; nt < 8; nt++) {
                int d = dbase + nt * 8 + (lane & 3) * 2;
                if (r0 < n)
                    *(float2*)(out + (size_t)r0 * DD + d) = make_float2(acc[nt][0], acc[nt][1]);
                if (r0 + 8 < n)
                    *(float2*)(out + (size_t)(r0 + 8) * DD + d) = make_float2(acc[nt][2], acc[nt][3]);
            }
        }
        cur ^= 1; it++; t = tn;
    }
}

// ---------------- host launcher ----------------
extern "C" void kernel_launch(void* const* d_in, const int* in_sizes, int n_in,
                              void* d_out, int out_size) {
    const int*   adj = (const int*)d_in[0];    // [2, N*K]: row 0 = src
    const float* x   = (const float*)d_in[1];  // [N, 512]
    const float* qw  = (const float*)d_in[2];  // [32, 512]
    const float* kw  = (const float*)d_in[3];  // [32, 512]
    const float* eg  = (const float*)d_in[4];  // [1, 32]
    const float* vw  = (const float*)d_in[5];  // [512, 32]
    float* out = (float*)d_out;

    int n = in_sizes[1] / DD;
    if (n > N_MAX) n = N_MAX;
    if (n <= 0) return;

    int nsm = 148;
    cudaDeviceGetAttribute(&nsm, cudaDevAttrMultiProcessorCount, 0);

    cudaFuncSetAttribute(gemm1_kernel, cudaFuncAttributeMaxDynamicSharedMemorySize, G1_SMEM);
    gemm1_kernel<<<2 * nsm, 256, G1_SMEM>>>(x, qw, kw, n);

    // attn + gemm2 launched with programmatic stream serialization (PDL)
    cudaLaunchAttribute pdl[1];
    pdl[0].id = cudaLaunchAttributeProgrammaticStreamSerialization;
    pdl[0].val.programmaticStreamSerializationAllowed = 1;

    {
        cudaLaunchConfig_t cfg = {};
        cfg.gridDim  = dim3(4 * nsm);
        cfg.blockDim = dim3(256);
        cfg.attrs = pdl;
        cfg.numAttrs = 1;
        cudaLaunchKernelEx(&cfg, attn_kernel, adj, eg, n);
    }

    cudaFuncSetAttribute(gemm2_kernel, cudaFuncAttributeMaxDynamicSharedMemorySize, G2_SMEM);
    {
        cudaLaunchConfig_t cfg = {};
        cfg.gridDim  = dim3(nsm);
        cfg.blockDim = dim3(512);
        cfg.dynamicSmemBytes = G2_SMEM;
        cfg.attrs = pdl;
        cfg.numAttrs = 1;
        cudaLaunchKernelEx(&cfg, gemm2_kernel, out, vw, n);
    }
}

// round 16
// speedup vs baseline: 1.0810x; 1.0810x over previous
#include <cuda_runtime.h>
#include <cuda_bf16.h>
#include <cstdint>

#define N_MAX 100000
#define DD 512
#define HH 32

// ---------------- scratch (static __device__, allocation-free) ----------------
static __device__ __nv_bfloat16 g_qemb_bf[N_MAX * HH];
static __device__ __nv_bfloat16 g_kemb_bf[N_MAX * HH];
static __device__ __nv_bfloat16 g_attn_bf[N_MAX * HH];
static __device__ int           g_ctr1;              // gemm1 dynamic tile counter (static-init 0)

// ---------------- helpers ----------------
__device__ __forceinline__ float nonneg(float w) { return w > 0.f ? w + 1.f : __expf(w); }

__device__ __forceinline__ uint32_t s2u(const void* p) {
    return (uint32_t)__cvta_generic_to_shared(p);
}

__device__ __forceinline__ void ldsm4(uint32_t (&r)[4], uint32_t addr) {
    asm volatile("ldmatrix.sync.aligned.m8n8.x4.shared.b16 {%0,%1,%2,%3}, [%4];"
                 : "=r"(r[0]), "=r"(r[1]), "=r"(r[2]), "=r"(r[3]) : "r"(addr));
}

__device__ __forceinline__ void mma16816(float (&d)[4], const uint32_t (&a)[4],
                                         uint32_t b0, uint32_t b1) {
    asm volatile(
        "mma.sync.aligned.m16n8k16.row.col.f32.bf16.bf16.f32 "
        "{%0,%1,%2,%3}, {%4,%5,%6,%7}, {%8,%9}, {%0,%1,%2,%3};"
        : "+f"(d[0]), "+f"(d[1]), "+f"(d[2]), "+f"(d[3])
        : "r"(a[0]), "r"(a[1]), "r"(a[2]), "r"(a[3]), "r"(b0), "r"(b1));
}

__device__ __forceinline__ void cp_async16(void* s, const void* g) {
    asm volatile("cp.async.cg.shared.global [%0], [%1], 16;"
                 :: "r"(s2u(s)), "l"(g));
}
__device__ __forceinline__ void cp_commit() { asm volatile("cp.async.commit_group;"); }
template <int NN>
__device__ __forceinline__ void cp_wait() { asm volatile("cp.async.wait_group %0;" :: "n"(NN)); }

__device__ __forceinline__ uint32_t bf2u(float a, float b) {
    __nv_bfloat162 p = __floats2bfloat162_rn(a, b);
    return *(uint32_t*)&p;
}

__device__ __forceinline__ void pdl_trigger() {
    asm volatile("griddepcontrol.launch_dependents;" ::: "memory");
}
__device__ __forceinline__ void pdl_wait() {
    asm volatile("griddepcontrol.wait;" ::: "memory");
}

// ---------------- K1: GEMM1  qk_emb = x @ Wqk^T  (mma.sync bf16, XOR swizzle) ----------------
// 256 thr, 2 CTAs/SM (measured best). W 64KB XOR-swizzled. x dbuf bf16 tiles.
// STS-first mainloop; warp tile 32 rows x 32 ch. Dynamic tiles via g_ctr1.
// Epilogue: BOTH q and k stored bf16 (identical paths).
#define G1_A0   65536
#define G1_A1   81920
#define G1_SMEM 98304

__global__ void __launch_bounds__(256, 2) gemm1_kernel(const float* __restrict__ x,
                                                       const float* __restrict__ qw,
                                                       const float* __restrict__ kw, int n) {
    extern __shared__ __align__(16) char sm[];
    __shared__ int stile;
    const int tid  = threadIdx.x;
    const int lane = tid & 31;
    const int warp = tid >> 5;

    // one-time: W = nonneg(qw/kw)/512 -> bf16 smem, row ch = 1024B, XOR swizzle
    for (int u = tid; u < 4096; u += 256) {
        int ch = u >> 6, seg = u & 63;
        const float* src = (ch < 32) ? (qw + ch * DD) : (kw + (ch - 32) * DD);
        float4 f0 = __ldg((const float4*)(src + seg * 8));
        float4 f1 = __ldg((const float4*)(src + seg * 8) + 1);
        const float sc = 1.f / (float)DD;
        uint4 pk;
        pk.x = bf2u(nonneg(f0.x) * sc, nonneg(f0.y) * sc);
        pk.y = bf2u(nonneg(f0.z) * sc, nonneg(f0.w) * sc);
        pk.z = bf2u(nonneg(f1.x) * sc, nonneg(f1.y) * sc);
        pk.w = bf2u(nonneg(f1.z) * sc, nonneg(f1.w) * sc);
        *(uint4*)(sm + ch * 1024 + ((seg * 16) ^ ((ch & 7) << 4))) = pk;
    }

    const int mrow = (warp & 3) * 32;  // row slice within 128-row tile
    const int chb  = (warp >> 2) * 32; // ch slice: warps 0-3 -> q, 4-7 -> k
    const uint32_t swz  = (uint32_t)((lane & 7) << 4);
    const uint32_t wrow = s2u(sm) + (uint32_t)(chb + (lane & 7) + ((lane >> 4) << 3)) * 1024u;
    const uint32_t whi  = (uint32_t)(((lane >> 3) & 1) << 4);
    const uint32_t ahi  = (uint32_t)(((lane >> 4) & 1) << 4);

    const int ntiles = (n + 127) >> 7;
    if (tid == 0) stile = atomicAdd(&g_ctr1, 1);
    __syncthreads();  // W ready + stile visible
    int tile = stile;

    while (tile < ntiles) {
        const int row0 = tile << 7;
        float acc[2][4][4];
        #pragma unroll
        for (int m = 0; m < 2; m++)
            #pragma unroll
            for (int nt = 0; nt < 4; nt++)
                #pragma unroll
                for (int j = 0; j < 4; j++) acc[m][nt][j] = 0.f;

        float4 v[4][2];
        // prologue: LDG(0) -> STS buf0 -> LDG(1)
        #pragma unroll
        for (int u = 0; u < 4; u++) {
            int idx = tid + (u << 8);
            int row = idx >> 3, seg = idx & 7;
            int gr = row0 + row; if (gr >= n) gr = n - 1;
            const float4* src = (const float4*)(x + (size_t)gr * DD + seg * 8);
            v[u][0] = __ldg(src); v[u][1] = __ldg(src + 1);
        }
        #pragma unroll
        for (int u = 0; u < 4; u++) {
            int idx = tid + (u << 8);
            int row = idx >> 3, seg = idx & 7;
            uint4 pk;
            pk.x = bf2u(v[u][0].x, v[u][0].y); pk.y = bf2u(v[u][0].z, v[u][0].w);
            pk.z = bf2u(v[u][1].x, v[u][1].y); pk.w = bf2u(v[u][1].z, v[u][1].w);
            *(uint4*)(sm + G1_A0 + row * 128 + ((seg * 16) ^ ((row & 7) << 4))) = pk;
        }
        #pragma unroll
        for (int u = 0; u < 4; u++) {
            int idx = tid + (u << 8);
            int row = idx >> 3, seg = idx & 7;
            int gr = row0 + row; if (gr >= n) gr = n - 1;
            const float4* src = (const float4*)(x + (size_t)gr * DD + 64 + seg * 8);
            v[u][0] = __ldg(src); v[u][1] = __ldg(src + 1);
        }
        __syncthreads();

        #pragma unroll 1
        for (int c = 0; c < 8; c++) {
            if (c < 7) {  // STS chunk c+1 (regs landed one full iteration ago)
                char* nbuf = sm + ((c & 1) ? G1_A0 : G1_A1);
                #pragma unroll
                for (int u = 0; u < 4; u++) {
                    int idx = tid + (u << 8);
                    int row = idx >> 3, seg = idx & 7;
                    uint4 pk;
                    pk.x = bf2u(v[u][0].x, v[u][0].y); pk.y = bf2u(v[u][0].z, v[u][0].w);
                    pk.z = bf2u(v[u][1].x, v[u][1].y); pk.w = bf2u(v[u][1].z, v[u][1].w);
                    *(uint4*)(nbuf + row * 128 + ((seg * 16) ^ ((row & 7) << 4))) = pk;
                }
            }
            if (c < 6) {  // LDG chunk c+2
                #pragma unroll
                for (int u = 0; u < 4; u++) {
                    int idx = tid + (u << 8);
                    int row = idx >> 3, seg = idx & 7;
                    int gr = row0 + row; if (gr >= n) gr = n - 1;
                    const float4* src = (const float4*)(x + (size_t)gr * DD + (c + 2) * 64 + seg * 8);
                    v[u][0] = __ldg(src); v[u][1] = __ldg(src + 1);
                }
            }
            // MMA on chunk c
            const uint32_t abase = s2u(sm) + (uint32_t)((c & 1) ? G1_A1 : G1_A0);
            const uint32_t arow0 = abase + (uint32_t)(mrow + (lane & 15)) * 128u;
            #pragma unroll
            for (int ks = 0; ks < 4; ks++) {
                uint32_t a0[4], a1[4], b0[4], b1[4];
                uint32_t akb = ((uint32_t)(ks * 32) + ahi) ^ swz;
                uint32_t wkb = (uint32_t)(c * 128) + (((uint32_t)(ks * 32) + whi) ^ swz);
                ldsm4(a0, arow0 + akb);
                ldsm4(a1, arow0 + 16u * 128u + akb);
                ldsm4(b0, wrow + wkb);
                ldsm4(b1, wrow + 16u * 1024u + wkb);
                mma16816(acc[0][0], a0, b0[0], b0[1]);
                mma16816(acc[0][1], a0, b0[2], b0[3]);
                mma16816(acc[0][2], a0, b1[0], b1[1]);
                mma16816(acc[0][3], a0, b1[2], b1[3]);
                mma16816(acc[1][0], a1, b0[0], b0[1]);
                mma16816(acc[1][1], a1, b0[2], b0[3]);
                mma16816(acc[1][2], a1, b1[0], b1[1]);
                mma16816(acc[1][3], a1, b1[2], b1[3]);
            }
            __syncthreads();
        }

        // epilogue: warps 0-3 -> q bf16, warps 4-7 -> k bf16
        {
            __nv_bfloat16* dst = (warp < 4) ? g_qemb_bf : g_kemb_bf;
            #pragma unroll
            for (int m = 0; m < 2; m++) {
                int r0 = row0 + mrow + m * 16 + (lane >> 2);
                #pragma unroll
                for (int nt = 0; nt < 4; nt++) {
                    int ch = nt * 8 + (lane & 3) * 2;
                    if (r0 < n)
                        *(uint32_t*)(dst + (size_t)r0 * HH + ch) = bf2u(acc[m][nt][0], acc[m][nt][1]);
                    if (r0 + 8 < n)
                        *(uint32_t*)(dst + (size_t)(r0 + 8) * HH + ch) = bf2u(acc[m][nt][2], acc[m][nt][3]);
                }
            }
        }

        if (tid == 0) stile = atomicAdd(&g_ctr1, 1);
        __syncthreads();
        tile = stile;
    }
    pdl_trigger();
}

// ---------------- K2: gather + attention normalize (wide gathers, 4-node unroll) ----------------
// Warp per 4 nodes: 32 outstanding uint2 gathers. lane = (jg = lane>>3, hp = lane&7).
// q now bf16 (uint2 per 4 heads). PDL: waits for gemm1; resets g_ctr1.
__global__ void __launch_bounds__(256) attn_kernel(const int* __restrict__ src,
                                                   const float* __restrict__ eg, int n) {
    const int lane = threadIdx.x & 31;
    const int jg   = lane >> 3;
    const int hp   = lane & 7;
    const int gw   = (blockIdx.x * blockDim.x + threadIdx.x) >> 5;
    const int nw   = (gridDim.x * blockDim.x) >> 5;
    float4 eraw = __ldg((const float4*)(eg + hp * 4));
    const float4 ego = make_float4(nonneg(eraw.x), nonneg(eraw.y), nonneg(eraw.z), nonneg(eraw.w));
    const float k1 = 1.f / 32.f;

    pdl_wait();  // gemm1 complete: k_emb/q_emb valid, g_ctr1 no longer read
    if (blockIdx.x == 0 && threadIdx.x == 0) g_ctr1 = 0;

    for (int node = gw * 4; node < n; node += nw * 4) {
        int nd[4];
        #pragma unroll
        for (int u = 0; u < 4; u++) nd[u] = (node + u < n) ? node + u : node;

        int s[4];
        #pragma unroll
        for (int u = 0; u < 4; u++) s[u] = src[(size_t)nd[u] * 32 + lane];

        float ac[4][4];
        #pragma unroll
        for (int u = 0; u < 4; u++)
            #pragma unroll
            for (int j = 0; j < 4; j++) ac[u][j] = 0.f;

        #pragma unroll
        for (int i = 0; i < 8; i++) {
            #pragma unroll
            for (int u = 0; u < 4; u++) {
                int sj = __shfl_sync(0xffffffffu, s[u], i * 4 + jg);
                uint2 kv = __ldg((const uint2*)(g_kemb_bf + (size_t)sj * HH + hp * 4));
                float2 f0 = __bfloat1622float2(*(__nv_bfloat162*)&kv.x);
                float2 f1 = __bfloat1622float2(*(__nv_bfloat162*)&kv.y);
                ac[u][0] += f0.x; ac[u][1] += f0.y; ac[u][2] += f1.x; ac[u][3] += f1.y;
            }
        }
        #pragma unroll
        for (int u = 0; u < 4; u++)
            #pragma unroll
            for (int j = 0; j < 4; j++) {
                ac[u][j] += __shfl_xor_sync(0xffffffffu, ac[u][j], 8);
                ac[u][j] += __shfl_xor_sync(0xffffffffu, ac[u][j], 16);
            }

        float sc[4][4], nsum[4];
        #pragma unroll
        for (int u = 0; u < 4; u++) {
            uint2 qv = __ldg((const uint2*)(g_qemb_bf + (size_t)nd[u] * HH + hp * 4));
            float2 q0 = __bfloat1622float2(*(__nv_bfloat162*)&qv.x);
            float2 q1 = __bfloat1622float2(*(__nv_bfloat162*)&qv.y);
            sc[u][0] = ego.x * q0.x * q0.x + q0.x * ac[u][0] * k1;
            sc[u][1] = ego.y * q0.y * q0.y + q0.y * ac[u][1] * k1;
            sc[u][2] = ego.z * q1.x * q1.x + q1.x * ac[u][2] * k1;
            sc[u][3] = ego.w * q1.y * q1.y + q1.y * ac[u][3] * k1;
            nsum[u] = (sc[u][0] + sc[u][1]) + (sc[u][2] + sc[u][3]);
        }
        #pragma unroll
        for (int u = 0; u < 4; u++) {
            nsum[u] += __shfl_xor_sync(0xffffffffu, nsum[u], 1);
            nsum[u] += __shfl_xor_sync(0xffffffffu, nsum[u], 2);
            nsum[u] += __shfl_xor_sync(0xffffffffu, nsum[u], 4);
        }

        if (jg == 0) {
            #pragma unroll
            for (int u = 0; u < 4; u++) {
                if (u == 0 || node + u < n) {
                    float inv = 1.f / (nsum[u] + 1e-9f);
                    uint2 pk;
                    pk.x = bf2u(sc[u][0] * inv, sc[u][1] * inv);
                    pk.y = bf2u(sc[u][2] * inv, sc[u][3] * inv);
                    *(uint2*)(g_attn_bf + (size_t)nd[u] * HH + hp * 4) = pk;
                }
            }
        }
    }
    pdl_trigger();
}

// ---------------- K3: GEMM2  out = attn @ V'  (mma.sync bf16, V frags hoisted) ----------------
// 512 thr, 16 warps. Warp = 16 nodes x 64 d; full D=512 coverage. V frags in registers.
// PDL: V prologue overlaps attn's tail; waits before reading g_attn_bf.
#define G2_VPITCH 80
#define G2_A0     40960
#define G2_A1     61440
#define G2_SMEM   81920

__global__ void __launch_bounds__(512, 1) gemm2_kernel(float* __restrict__ out,
                                                       const float* __restrict__ vw, int n) {
    extern __shared__ __align__(16) char sm[];
    const int tid  = threadIdx.x;
    const int lane = tid & 31;
    const int warp = tid >> 5;

    // one-time: V [512][32] f32 -> nonneg -> bf16 smem, pitch 80B (runs under PDL overlap)
    for (int i = tid; i < 2048; i += 512) {
        int d = i >> 2, seg = i & 3;
        const float4* src = (const float4*)(vw + d * HH + seg * 8);
        float4 f0 = __ldg(src), f1 = __ldg(src + 1);
        uint4 pk;
        pk.x = bf2u(nonneg(f0.x), nonneg(f0.y));
        pk.y = bf2u(nonneg(f0.z), nonneg(f0.w));
        pk.z = bf2u(nonneg(f1.x), nonneg(f1.y));
        pk.w = bf2u(nonneg(f1.z), nonneg(f1.w));
        *(uint4*)(sm + d * G2_VPITCH + seg * 16) = pk;
    }
    __syncthreads();

    const int nsl   = (warp & 1) * 16;   // node sub-slice within 32-node subtile
    const int dbase = (warp >> 1) * 64;  // d slice: 8 groups x 64 = 512

    // hoist V fragments: [kstep][ptile][4 regs]
    uint32_t bf[2][4][4];
    {
        uint32_t vb = s2u(sm) + (uint32_t)(dbase + (lane & 7) + ((lane >> 4) << 3)) * G2_VPITCH
                    + (uint32_t)(((lane >> 3) & 1) << 4);
        #pragma unroll
        for (int ks = 0; ks < 2; ks++)
            #pragma unroll
            for (int p = 0; p < 4; p++)
                ldsm4(bf[ks][p], vb + (uint32_t)(p * 16 * G2_VPITCH) + (uint32_t)(ks * 32));
    }
    __syncthreads();

    pdl_wait();  // attn complete: g_attn_bf valid

    const int ntiles = (n + 255) >> 8;
    int t = blockIdx.x;
    if (t < ntiles) {
        int n0 = t << 8;
        #pragma unroll
        for (int u = 0; u < 2; u++) {
            int idx = tid + (u << 9);
            int row = idx >> 2, seg = idx & 3;
            int node = n0 + row; if (node >= n) node = n - 1;
            cp_async16(sm + G2_A0 + row * G2_VPITCH + seg * 16,
                       g_attn_bf + (size_t)node * HH + seg * 8);
        }
        cp_commit();
    }
    int cur = 0;
    for (; t < ntiles; t += (int)gridDim.x) {
        int tn = t + (int)gridDim.x;
        if (tn < ntiles) {
            int n0 = tn << 8;
            char* dst = sm + (cur ? G2_A0 : G2_A1);
            #pragma unroll
            for (int u = 0; u < 2; u++) {
                int idx = tid + (u << 9);
                int row = idx >> 2, seg = idx & 3;
                int node = n0 + row; if (node >= n) node = n - 1;
                cp_async16(dst + row * G2_VPITCH + seg * 16,
                           g_attn_bf + (size_t)node * HH + seg * 8);
            }
            cp_commit();
            cp_wait<1>();
        } else {
            cp_wait<0>();
        }
        __syncthreads();

        const char* ab = sm + (cur ? G2_A1 : G2_A0);
        const int node0 = t << 8;
        #pragma unroll 1
        for (int sub = 0; sub < 8; sub++) {
            uint32_t a[2][4];
            uint32_t aaddr = s2u(ab) + (uint32_t)((sub * 32 + nsl + (lane & 15)) * G2_VPITCH)
                           + (uint32_t)(((lane >> 4) & 1) << 4);
            ldsm4(a[0], aaddr);
            ldsm4(a[1], aaddr + 32);

            float acc[8][4];
            #pragma unroll
            for (int nt = 0; nt < 8; nt++)
                #pragma unroll
                for (int j = 0; j < 4; j++) acc[nt][j] = 0.f;

            #pragma unroll
            for (int nt = 0; nt < 8; nt++) {
                mma16816(acc[nt], a[0], bf[0][nt >> 1][(nt & 1) * 2], bf[0][nt >> 1][(nt & 1) * 2 + 1]);
                mma16816(acc[nt], a[1], bf[1][nt >> 1][(nt & 1) * 2], bf[1][nt >> 1][(nt & 1) * 2 + 1]);
            }

            int r0 = node0 + sub * 32 + nsl + (lane >> 2);
            #pragma unroll
            for (int nt = 0; nt < 8; nt++) {
                int d = dbase + nt * 8 + (lane & 3) * 2;
                if (r0 < n)
                    *(float2*)(out + (size_t)r0 * DD + d) = make_float2(acc[nt][0], acc[nt][1]);
                if (r0 + 8 < n)
                    *(float2*)(out + (size_t)(r0 + 8) * DD + d) = make_float2(acc[nt][2], acc[nt][3]);
            }
        }
        cur ^= 1;
        __syncthreads();
    }
}

// ---------------- host launcher ----------------
extern "C" void kernel_launch(void* const* d_in, const int* in_sizes, int n_in,
                              void* d_out, int out_size) {
    const int*   adj = (const int*)d_in[0];    // [2, N*K]: row 0 = src
    const float* x   = (const float*)d_in[1];  // [N, 512]
    const float* qw  = (const float*)d_in[2];  // [32, 512]
    const float* kw  = (const float*)d_in[3];  // [32, 512]
    const float* eg  = (const float*)d_in[4];  // [1, 32]
    const float* vw  = (const float*)d_in[5];  // [512, 32]
    float* out = (float*)d_out;

    int n = in_sizes[1] / DD;
    if (n > N_MAX) n = N_MAX;
    if (n <= 0) return;

    int nsm = 148;
    cudaDeviceGetAttribute(&nsm, cudaDevAttrMultiProcessorCount, 0);

    cudaFuncSetAttribute(gemm1_kernel, cudaFuncAttributeMaxDynamicSharedMemorySize, G1_SMEM);
    gemm1_kernel<<<2 * nsm, 256, G1_SMEM>>>(x, qw, kw, n);

    // attn + gemm2 launched with programmatic stream serialization (PDL)
    cudaLaunchAttribute pdl[1];
    pdl[0].id = cudaLaunchAttributeProgrammaticStreamSerialization;
    pdl[0].val.programmaticStreamSerializationAllowed = 1;

    {
        cudaLaunchConfig_t cfg = {};
        cfg.gridDim  = dim3(8 * nsm);
        cfg.blockDim = dim3(256);
        cfg.attrs = pdl;
        cfg.numAttrs = 1;
        cudaLaunchKernelEx(&cfg, attn_kernel, adj, eg, n);
    }

    cudaFuncSetAttribute(gemm2_kernel, cudaFuncAttributeMaxDynamicSharedMemorySize, G2_SMEM);
    {
        cudaLaunchConfig_t cfg = {};
        cfg.gridDim  = dim3(nsm);
        cfg.blockDim = dim3(512);
        cfg.dynamicSmemBytes = G2_SMEM;
        cfg.attrs = pdl;
        cfg.numAttrs = 1;
        cudaLaunchKernelEx(&cfg, gemm2_kernel, out, vw, n);
    }
}

// round 17
// speedup vs baseline: 1.1342x; 1.0492x over previous
#include <cuda_runtime.h>
#include <cuda_bf16.h>
#include <cstdint>

#define N_MAX 100000
#define DD 512
#define HH 32

// ---------------- scratch (static __device__, allocation-free) ----------------
static __device__ __nv_bfloat16 g_wqk_bf[64 * DD];   // prep output: nonneg(W)/512, bf16
static __device__ float         g_qemb[N_MAX * HH];  // f32
static __device__ __nv_bfloat16 g_kemb_bf[N_MAX * HH];
static __device__ __nv_bfloat16 g_attn_bf[N_MAX * HH];
static __device__ int           g_ctr1;              // gemm1 dynamic tile counter (static-init 0)

// ---------------- helpers ----------------
__device__ __forceinline__ float nonneg(float w) { return w > 0.f ? w + 1.f : __expf(w); }

__device__ __forceinline__ uint32_t s2u(const void* p) {
    return (uint32_t)__cvta_generic_to_shared(p);
}

__device__ __forceinline__ void ldsm4(uint32_t (&r)[4], uint32_t addr) {
    asm volatile("ldmatrix.sync.aligned.m8n8.x4.shared.b16 {%0,%1,%2,%3}, [%4];"
                 : "=r"(r[0]), "=r"(r[1]), "=r"(r[2]), "=r"(r[3]) : "r"(addr));
}

__device__ __forceinline__ void mma16816(float (&d)[4], const uint32_t (&a)[4],
                                         uint32_t b0, uint32_t b1) {
    asm volatile(
        "mma.sync.aligned.m16n8k16.row.col.f32.bf16.bf16.f32 "
        "{%0,%1,%2,%3}, {%4,%5,%6,%7}, {%8,%9}, {%0,%1,%2,%3};"
        : "+f"(d[0]), "+f"(d[1]), "+f"(d[2]), "+f"(d[3])
        : "r"(a[0]), "r"(a[1]), "r"(a[2]), "r"(a[3]), "r"(b0), "r"(b1));
}

__device__ __forceinline__ void cp_async16(void* s, const void* g) {
    asm volatile("cp.async.cg.shared.global [%0], [%1], 16;"
                 :: "r"(s2u(s)), "l"(g));
}
__device__ __forceinline__ void cp_commit() { asm volatile("cp.async.commit_group;"); }
template <int NN>
__device__ __forceinline__ void cp_wait() { asm volatile("cp.async.wait_group %0;" :: "n"(NN)); }

__device__ __forceinline__ uint32_t bf2u(float a, float b) {
    __nv_bfloat162 p = __floats2bfloat162_rn(a, b);
    return *(uint32_t*)&p;
}

__device__ __forceinline__ void pdl_trigger() {
    asm volatile("griddepcontrol.launch_dependents;" ::: "memory");
}
__device__ __forceinline__ void pdl_wait() {
    asm volatile("griddepcontrol.wait;" ::: "memory");
}

// ---------------- K0: W preprocessing (once per replay; 64KB output stays L2-resident) ----------------
__global__ void __launch_bounds__(256) prep_kernel(const float* __restrict__ qw,
                                                   const float* __restrict__ kw) {
    int i = blockIdx.x * blockDim.x + threadIdx.x;  // 32768 elems
    float w = (i < 32 * DD) ? __ldg(qw + i) : __ldg(kw + i - 32 * DD);
    g_wqk_bf[i] = __float2bfloat16(nonneg(w) * (1.f / (float)DD));
    pdl_trigger();
}

// ---------------- K1: GEMM1  qk_emb = x @ Wqk^T  (mma.sync bf16, XOR swizzle) ----------------
// 256 thr, 2 CTAs/SM. W loaded from L2-resident g_wqk_bf (64KB bf16, no per-CTA conversion).
// x double-buffered bf16 tiles; STS-first mainloop; warp tile 32 rows x 32 ch.
// Dynamic tiles via g_ctr1 (reset downstream by attn).
#define G1_A0   65536
#define G1_A1   81920
#define G1_SMEM 98304

__global__ void __launch_bounds__(256, 2) gemm1_kernel(const float* __restrict__ x, int n) {
    extern __shared__ __align__(16) char sm[];
    __shared__ int stile;
    const int tid  = threadIdx.x;
    const int lane = tid & 31;
    const int warp = tid >> 5;

    pdl_wait();  // prep complete: g_wqk_bf valid

    // one-time: W bf16 -> smem, row ch = 1024B, XOR swizzle (uint4 = 8 k-values)
    for (int u = tid; u < 4096; u += 256) {
        int ch = u >> 6, seg = u & 63;
        uint4 pk = *(const uint4*)(g_wqk_bf + ch * DD + seg * 8);
        *(uint4*)(sm + ch * 1024 + ((seg * 16) ^ ((ch & 7) << 4))) = pk;
    }

    const int mrow = (warp & 3) * 32;  // row slice within 128-row tile
    const int chb  = (warp >> 2) * 32; // ch slice: warps 0-3 -> q, 4-7 -> k
    const uint32_t swz  = (uint32_t)((lane & 7) << 4);
    const uint32_t wrow = s2u(sm) + (uint32_t)(chb + (lane & 7) + ((lane >> 4) << 3)) * 1024u;
    const uint32_t whi  = (uint32_t)(((lane >> 3) & 1) << 4);
    const uint32_t ahi  = (uint32_t)(((lane >> 4) & 1) << 4);

    const int ntiles = (n + 127) >> 7;
    if (tid == 0) stile = atomicAdd(&g_ctr1, 1);
    __syncthreads();  // W ready + stile visible
    int tile = stile;

    while (tile < ntiles) {
        const int row0 = tile << 7;
        float acc[2][4][4];
        #pragma unroll
        for (int m = 0; m < 2; m++)
            #pragma unroll
            for (int nt = 0; nt < 4; nt++)
                #pragma unroll
                for (int j = 0; j < 4; j++) acc[m][nt][j] = 0.f;

        float4 v[4][2];
        // prologue: LDG(0) -> STS buf0 -> LDG(1)
        #pragma unroll
        for (int u = 0; u < 4; u++) {
            int idx = tid + (u << 8);
            int row = idx >> 3, seg = idx & 7;
            int gr = row0 + row; if (gr >= n) gr = n - 1;
            const float4* src = (const float4*)(x + (size_t)gr * DD + seg * 8);
            v[u][0] = __ldg(src); v[u][1] = __ldg(src + 1);
        }
        #pragma unroll
        for (int u = 0; u < 4; u++) {
            int idx = tid + (u << 8);
            int row = idx >> 3, seg = idx & 7;
            uint4 pk;
            pk.x = bf2u(v[u][0].x, v[u][0].y); pk.y = bf2u(v[u][0].z, v[u][0].w);
            pk.z = bf2u(v[u][1].x, v[u][1].y); pk.w = bf2u(v[u][1].z, v[u][1].w);
            *(uint4*)(sm + G1_A0 + row * 128 + ((seg * 16) ^ ((row & 7) << 4))) = pk;
        }
        #pragma unroll
        for (int u = 0; u < 4; u++) {
            int idx = tid + (u << 8);
            int row = idx >> 3, seg = idx & 7;
            int gr = row0 + row; if (gr >= n) gr = n - 1;
            const float4* src = (const float4*)(x + (size_t)gr * DD + 64 + seg * 8);
            v[u][0] = __ldg(src); v[u][1] = __ldg(src + 1);
        }
        __syncthreads();

        #pragma unroll 1
        for (int c = 0; c < 8; c++) {
            if (c < 7) {  // STS chunk c+1 (regs landed one full iteration ago)
                char* nbuf = sm + ((c & 1) ? G1_A0 : G1_A1);
                #pragma unroll
                for (int u = 0; u < 4; u++) {
                    int idx = tid + (u << 8);
                    int row = idx >> 3, seg = idx & 7;
                    uint4 pk;
                    pk.x = bf2u(v[u][0].x, v[u][0].y); pk.y = bf2u(v[u][0].z, v[u][0].w);
                    pk.z = bf2u(v[u][1].x, v[u][1].y); pk.w = bf2u(v[u][1].z, v[u][1].w);
                    *(uint4*)(nbuf + row * 128 + ((seg * 16) ^ ((row & 7) << 4))) = pk;
                }
            }
            if (c < 6) {  // LDG chunk c+2
                #pragma unroll
                for (int u = 0; u < 4; u++) {
                    int idx = tid + (u << 8);
                    int row = idx >> 3, seg = idx & 7;
                    int gr = row0 + row; if (gr >= n) gr = n - 1;
                    const float4* src = (const float4*)(x + (size_t)gr * DD + (c + 2) * 64 + seg * 8);
                    v[u][0] = __ldg(src); v[u][1] = __ldg(src + 1);
                }
            }
            // MMA on chunk c
            const uint32_t abase = s2u(sm) + (uint32_t)((c & 1) ? G1_A1 : G1_A0);
            const uint32_t arow0 = abase + (uint32_t)(mrow + (lane & 15)) * 128u;
            #pragma unroll
            for (int ks = 0; ks < 4; ks++) {
                uint32_t a0[4], a1[4], b0[4], b1[4];
                uint32_t akb = ((uint32_t)(ks * 32) + ahi) ^ swz;
                uint32_t wkb = (uint32_t)(c * 128) + (((uint32_t)(ks * 32) + whi) ^ swz);
                ldsm4(a0, arow0 + akb);
                ldsm4(a1, arow0 + 16u * 128u + akb);
                ldsm4(b0, wrow + wkb);
                ldsm4(b1, wrow + 16u * 1024u + wkb);
                mma16816(acc[0][0], a0, b0[0], b0[1]);
                mma16816(acc[0][1], a0, b0[2], b0[3]);
                mma16816(acc[0][2], a0, b1[0], b1[1]);
                mma16816(acc[0][3], a0, b1[2], b1[3]);
                mma16816(acc[1][0], a1, b0[0], b0[1]);
                mma16816(acc[1][1], a1, b0[2], b0[3]);
                mma16816(acc[1][2], a1, b1[0], b1[1]);
                mma16816(acc[1][3], a1, b1[2], b1[3]);
            }
            __syncthreads();
        }

        // epilogue: warps 0-3 -> q f32, warps 4-7 -> k bf16
        #pragma unroll
        for (int m = 0; m < 2; m++) {
            int r0 = row0 + mrow + m * 16 + (lane >> 2);
            #pragma unroll
            for (int nt = 0; nt < 4; nt++) {
                int ch = nt * 8 + (lane & 3) * 2;
                if (warp < 4) {
                    if (r0 < n)
                        *(float2*)(g_qemb + (size_t)r0 * HH + ch) = make_float2(acc[m][nt][0], acc[m][nt][1]);
                    if (r0 + 8 < n)
                        *(float2*)(g_qemb + (size_t)(r0 + 8) * HH + ch) = make_float2(acc[m][nt][2], acc[m][nt][3]);
                } else {
                    if (r0 < n)
                        *(uint32_t*)(g_kemb_bf + (size_t)r0 * HH + ch) = bf2u(acc[m][nt][0], acc[m][nt][1]);
                    if (r0 + 8 < n)
                        *(uint32_t*)(g_kemb_bf + (size_t)(r0 + 8) * HH + ch) = bf2u(acc[m][nt][2], acc[m][nt][3]);
                }
            }
        }

        if (tid == 0) stile = atomicAdd(&g_ctr1, 1);
        __syncthreads();
        tile = stile;
    }
    pdl_trigger();
}

// ---------------- K2: gather + attention normalize (wide gathers, 4-node unroll) ----------------
// Warp per 4 nodes: 32 outstanding uint2 gathers. lane = (jg = lane>>3, hp = lane&7).
// PDL: waits for gemm1 before touching k_emb/q_emb or resetting g_ctr1.
__global__ void __launch_bounds__(256) attn_kernel(const int* __restrict__ src,
                                                   const float* __restrict__ eg, int n) {
    const int lane = threadIdx.x & 31;
    const int jg   = lane >> 3;
    const int hp   = lane & 7;
    const int gw   = (blockIdx.x * blockDim.x + threadIdx.x) >> 5;
    const int nw   = (gridDim.x * blockDim.x) >> 5;
    float4 eraw = __ldg((const float4*)(eg + hp * 4));
    const float4 ego = make_float4(nonneg(eraw.x), nonneg(eraw.y), nonneg(eraw.z), nonneg(eraw.w));
    const float k1 = 1.f / 32.f;

    pdl_wait();  // gemm1 complete: k_emb/q_emb valid, g_ctr1 no longer read
    if (blockIdx.x == 0 && threadIdx.x == 0) g_ctr1 = 0;

    for (int node = gw * 4; node < n; node += nw * 4) {
        int nd[4];
        #pragma unroll
        for (int u = 0; u < 4; u++) nd[u] = (node + u < n) ? node + u : node;

        int s[4];
        #pragma unroll
        for (int u = 0; u < 4; u++) s[u] = src[(size_t)nd[u] * 32 + lane];

        float ac[4][4];
        #pragma unroll
        for (int u = 0; u < 4; u++)
            #pragma unroll
            for (int j = 0; j < 4; j++) ac[u][j] = 0.f;

        #pragma unroll
        for (int i = 0; i < 8; i++) {
            #pragma unroll
            for (int u = 0; u < 4; u++) {
                int sj = __shfl_sync(0xffffffffu, s[u], i * 4 + jg);
                uint2 kv = __ldg((const uint2*)(g_kemb_bf + (size_t)sj * HH + hp * 4));
                float2 f0 = __bfloat1622float2(*(__nv_bfloat162*)&kv.x);
                float2 f1 = __bfloat1622float2(*(__nv_bfloat162*)&kv.y);
                ac[u][0] += f0.x; ac[u][1] += f0.y; ac[u][2] += f1.x; ac[u][3] += f1.y;
            }
        }
        #pragma unroll
        for (int u = 0; u < 4; u++)
            #pragma unroll
            for (int j = 0; j < 4; j++) {
                ac[u][j] += __shfl_xor_sync(0xffffffffu, ac[u][j], 8);
                ac[u][j] += __shfl_xor_sync(0xffffffffu, ac[u][j], 16);
            }

        float sc[4][4], nsum[4];
        #pragma unroll
        for (int u = 0; u < 4; u++) {
            float4 q = *(const float4*)(g_qemb + (size_t)nd[u] * HH + hp * 4);
            sc[u][0] = ego.x * q.x * q.x + q.x * ac[u][0] * k1;
            sc[u][1] = ego.y * q.y * q.y + q.y * ac[u][1] * k1;
            sc[u][2] = ego.z * q.z * q.z + q.z * ac[u][2] * k1;
            sc[u][3] = ego.w * q.w * q.w + q.w * ac[u][3] * k1;
            nsum[u] = (sc[u][0] + sc[u][1]) + (sc[u][2] + sc[u][3]);
        }
        #pragma unroll
        for (int u = 0; u < 4; u++) {
            nsum[u] += __shfl_xor_sync(0xffffffffu, nsum[u], 1);
            nsum[u] += __shfl_xor_sync(0xffffffffu, nsum[u], 2);
            nsum[u] += __shfl_xor_sync(0xffffffffu, nsum[u], 4);
        }

        if (jg == 0) {
            #pragma unroll
            for (int u = 0; u < 4; u++) {
                if (u == 0 || node + u < n) {
                    float inv = 1.f / (nsum[u] + 1e-9f);
                    uint2 pk;
                    pk.x = bf2u(sc[u][0] * inv, sc[u][1] * inv);
                    pk.y = bf2u(sc[u][2] * inv, sc[u][3] * inv);
                    *(uint2*)(g_attn_bf + (size_t)nd[u] * HH + hp * 4) = pk;
                }
            }
        }
    }
    pdl_trigger();
}

// ---------------- K3: GEMM2  out = attn @ V'  (mma.sync bf16, V frags hoisted) ----------------
// 512 thr, 16 warps. Warp = 16 nodes x 64 d; full D=512 coverage. V frags in registers.
// PDL: V prologue overlaps attn's tail; waits before reading g_attn_bf.
#define G2_VPITCH 80
#define G2_A0     40960
#define G2_A1     61440
#define G2_SMEM   81920

__global__ void __launch_bounds__(512, 1) gemm2_kernel(float* __restrict__ out,
                                                       const float* __restrict__ vw, int n) {
    extern __shared__ __align__(16) char sm[];
    const int tid  = threadIdx.x;
    const int lane = tid & 31;
    const int warp = tid >> 5;

    // one-time: V [512][32] f32 -> nonneg -> bf16 smem, pitch 80B (runs under PDL overlap)
    for (int i = tid; i < 2048; i += 512) {
        int d = i >> 2, seg = i & 3;
        const float4* src = (const float4*)(vw + d * HH + seg * 8);
        float4 f0 = __ldg(src), f1 = __ldg(src + 1);
        uint4 pk;
        pk.x = bf2u(nonneg(f0.x), nonneg(f0.y));
        pk.y = bf2u(nonneg(f0.z), nonneg(f0.w));
        pk.z = bf2u(nonneg(f1.x), nonneg(f1.y));
        pk.w = bf2u(nonneg(f1.z), nonneg(f1.w));
        *(uint4*)(sm + d * G2_VPITCH + seg * 16) = pk;
    }
    __syncthreads();

    const int nsl   = (warp & 1) * 16;   // node sub-slice within 32-node subtile
    const int dbase = (warp >> 1) * 64;  // d slice: 8 groups x 64 = 512

    // hoist V fragments: [kstep][ptile][4 regs]
    uint32_t bf[2][4][4];
    {
        uint32_t vb = s2u(sm) + (uint32_t)(dbase + (lane & 7) + ((lane >> 4) << 3)) * G2_VPITCH
                    + (uint32_t)(((lane >> 3) & 1) << 4);
        #pragma unroll
        for (int ks = 0; ks < 2; ks++)
            #pragma unroll
            for (int p = 0; p < 4; p++)
                ldsm4(bf[ks][p], vb + (uint32_t)(p * 16 * G2_VPITCH) + (uint32_t)(ks * 32));
    }
    __syncthreads();

    pdl_wait();  // attn complete: g_attn_bf valid

    const int ntiles = (n + 255) >> 8;
    int t = blockIdx.x;
    if (t < ntiles) {
        int n0 = t << 8;
        #pragma unroll
        for (int u = 0; u < 2; u++) {
            int idx = tid + (u << 9);
            int row = idx >> 2, seg = idx & 3;
            int node = n0 + row; if (node >= n) node = n - 1;
            cp_async16(sm + G2_A0 + row * G2_VPITCH + seg * 16,
                       g_attn_bf + (size_t)node * HH + seg * 8);
        }
        cp_commit();
    }
    int cur = 0;
    for (; t < ntiles; t += (int)gridDim.x) {
        int tn = t + (int)gridDim.x;
        if (tn < ntiles) {
            int n0 = tn << 8;
            char* dst = sm + (cur ? G2_A0 : G2_A1);
            #pragma unroll
            for (int u = 0; u < 2; u++) {
                int idx = tid + (u << 9);
                int row = idx >> 2, seg = idx & 3;
                int node = n0 + row; if (node >= n) node = n - 1;
                cp_async16(dst + row * G2_VPITCH + seg * 16,
                           g_attn_bf + (size_t)node * HH + seg * 8);
            }
            cp_commit();
            cp_wait<1>();
        } else {
            cp_wait<0>();
        }
        __syncthreads();

        const char* ab = sm + (cur ? G2_A1 : G2_A0);
        const int node0 = t << 8;
        #pragma unroll 1
        for (int sub = 0; sub < 8; sub++) {
            uint32_t a[2][4];
            uint32_t aaddr = s2u(ab) + (uint32_t)((sub * 32 + nsl + (lane & 15)) * G2_VPITCH)
                           + (uint32_t)(((lane >> 4) & 1) << 4);
            ldsm4(a[0], aaddr);
            ldsm4(a[1], aaddr + 32);

            float acc[8][4];
            #pragma unroll
            for (int nt = 0; nt < 8; nt++)
                #pragma unroll
                for (int j = 0; j < 4; j++) acc[nt][j] = 0.f;

            #pragma unroll
            for (int nt = 0; nt < 8; nt++) {
                mma16816(acc[nt], a[0], bf[0][nt >> 1][(nt & 1) * 2], bf[0][nt >> 1][(nt & 1) * 2 + 1]);
                mma16816(acc[nt], a[1], bf[1][nt >> 1][(nt & 1) * 2], bf[1][nt >> 1][(nt & 1) * 2 + 1]);
            }

            int r0 = node0 + sub * 32 + nsl + (lane >> 2);
            #pragma unroll
            for (int nt = 0; nt < 8; nt++) {
                int d = dbase + nt * 8 + (lane & 3) * 2;
                if (r0 < n)
                    *(float2*)(out + (size_t)r0 * DD + d) = make_float2(acc[nt][0], acc[nt][1]);
                if (r0 + 8 < n)
                    *(float2*)(out + (size_t)(r0 + 8) * DD + d) = make_float2(acc[nt][2], acc[nt][3]);
            }
        }
        cur ^= 1;
        __syncthreads();
    }
}

// ---------------- host launcher ----------------
extern "C" void kernel_launch(void* const* d_in, const int* in_sizes, int n_in,
                              void* d_out, int out_size) {
    const int*   adj = (const int*)d_in[0];    // [2, N*K]: row 0 = src
    const float* x   = (const float*)d_in[1];  // [N, 512]
    const float* qw  = (const float*)d_in[2];  // [32, 512]
    const float* kw  = (const float*)d_in[3];  // [32, 512]
    const float* eg  = (const float*)d_in[4];  // [1, 32]
    const float* vw  = (const float*)d_in[5];  // [512, 32]
    float* out = (float*)d_out;

    int n = in_sizes[1] / DD;
    if (n > N_MAX) n = N_MAX;
    if (n <= 0) return;

    int nsm = 148;
    cudaDeviceGetAttribute(&nsm, cudaDevAttrMultiProcessorCount, 0);

    cudaLaunchAttribute pdl[1];
    pdl[0].id = cudaLaunchAttributeProgrammaticStreamSerialization;
    pdl[0].val.programmaticStreamSerializationAllowed = 1;

    prep_kernel<<<128, 256>>>(qw, kw);

    cudaFuncSetAttribute(gemm1_kernel, cudaFuncAttributeMaxDynamicSharedMemorySize, G1_SMEM);
    {
        cudaLaunchConfig_t cfg = {};
        cfg.gridDim  = dim3(2 * nsm);
        cfg.blockDim = dim3(256);
        cfg.dynamicSmemBytes = G1_SMEM;
        cfg.attrs = pdl;
        cfg.numAttrs = 1;
        cudaLaunchKernelEx(&cfg, gemm1_kernel, x, n);
    }

    {
        cudaLaunchConfig_t cfg = {};
        cfg.gridDim  = dim3(8 * nsm);
        cfg.blockDim = dim3(256);
        cfg.attrs = pdl;
        cfg.numAttrs = 1;
        cudaLaunchKernelEx(&cfg, attn_kernel, adj, eg, n);
    }

    cudaFuncSetAttribute(gemm2_kernel, cudaFuncAttributeMaxDynamicSharedMemorySize, G2_SMEM);
    {
        cudaLaunchConfig_t cfg = {};
        cfg.gridDim  = dim3(nsm);
        cfg.blockDim = dim3(512);
        cfg.dynamicSmemBytes = G2_SMEM;
        cfg.attrs = pdl;
        cfg.numAttrs = 1;
        cudaLaunchKernelEx(&cfg, gemm2_kernel, out, vw, n);
    }
}